// round 1
// baseline (speedup 1.0000x reference)
#include <cuda_runtime.h>
#include <cuda_fp16.h>
#include <cstdint>

// BitLinear: scale = mean|W|; Wq = round(W/(scale+eps)); y = (x @ Wq^T) * scale
// x: [8192, 4096] f32 (flattened 4x2048), W: [4096, 4096] f32, out: [8192, 4096] f32
//
// Pipeline:
//   1) k_absum_rows + k_finalize_scale : deterministic two-stage mean(|W|)
//   2) k_quant_w  : Wq fp16 (exact small integers) -> g_Wq (32MB, ~L2 resident)
//   3) k_conv_x   : x -> fp16 -> g_Xh
//   4) k_gemm     : 128x128x32 tiles, mma.sync m16n8k16 f16->f32, cp.async double buffer

#define EPS_F 1e-5f
#define BM 128
#define BN 128
#define BK 32
#define KSTRIDE 40  // padded smem row stride (halves) -> conflict-free ldmatrix

__device__ float  g_partial[4096];
__device__ float  g_scale;
__device__ float  g_inv;
__device__ __half g_Wq[4096u * 4096u];   // 32 MB
__device__ __half g_Xh[8192u * 4096u];   // 64 MB

// ---------------------------------------------------------------- reductions
__global__ void k_absum_rows(const float* __restrict__ W) {
    int row = blockIdx.x;
    const float* p = W + (size_t)row * 4096;
    float s = 0.f;
    for (int i = threadIdx.x; i < 4096; i += 256) s += fabsf(p[i]);
    for (int o = 16; o > 0; o >>= 1) s += __shfl_down_sync(0xffffffffu, s, o);
    __shared__ float sm[8];
    if ((threadIdx.x & 31) == 0) sm[threadIdx.x >> 5] = s;
    __syncthreads();
    if (threadIdx.x < 8) {
        float v = sm[threadIdx.x];
        for (int o = 4; o > 0; o >>= 1) v += __shfl_down_sync(0xffu, v, o);
        if (threadIdx.x == 0) g_partial[row] = v;
    }
}

__global__ void k_finalize_scale() {
    float s = 0.f;
    for (int i = threadIdx.x; i < 4096; i += 256) s += g_partial[i];
    for (int o = 16; o > 0; o >>= 1) s += __shfl_down_sync(0xffffffffu, s, o);
    __shared__ float sm[8];
    if ((threadIdx.x & 31) == 0) sm[threadIdx.x >> 5] = s;
    __syncthreads();
    if (threadIdx.x < 8) {
        float v = sm[threadIdx.x];
        for (int o = 4; o > 0; o >>= 1) v += __shfl_down_sync(0xffu, v, o);
        if (threadIdx.x == 0) {
            float mean = v / 16777216.f;
            g_scale = mean;
            g_inv   = 1.f / (mean + EPS_F);
        }
    }
}

// ---------------------------------------------------------------- quant/conv
__global__ void k_quant_w(const float4* __restrict__ W4) {
    float inv = g_inv;
    int idx = blockIdx.x * 256 + threadIdx.x;     // 4,194,304 float4s
    float4 w = W4[idx];
    __half2* o = (__half2*)g_Wq + (size_t)idx * 2;
    o[0] = __floats2half2_rn(rintf(w.x * inv), rintf(w.y * inv));
    o[1] = __floats2half2_rn(rintf(w.z * inv), rintf(w.w * inv));
}

__global__ void k_conv_x(const float4* __restrict__ X4) {
    int idx = blockIdx.x * 256 + threadIdx.x;     // 8,388,608 float4s
    float4 v = X4[idx];
    __half2* o = (__half2*)g_Xh + (size_t)idx * 2;
    o[0] = __floats2half2_rn(v.x, v.y);
    o[1] = __floats2half2_rn(v.z, v.w);
}

// ---------------------------------------------------------------- GEMM
__device__ __forceinline__ uint32_t smem_u32(const void* p) {
    return (uint32_t)__cvta_generic_to_shared(p);
}
__device__ __forceinline__ void cp16(uint32_t dst, const void* src) {
    asm volatile("cp.async.cg.shared.global [%0], [%1], 16;\n" :: "r"(dst), "l"(src));
}
__device__ __forceinline__ void ldm4(uint32_t addr, uint32_t& r0, uint32_t& r1,
                                     uint32_t& r2, uint32_t& r3) {
    asm volatile("ldmatrix.sync.aligned.m8n8.x4.shared.b16 {%0,%1,%2,%3}, [%4];"
                 : "=r"(r0), "=r"(r1), "=r"(r2), "=r"(r3) : "r"(addr));
}
__device__ __forceinline__ void mma16816(float& c0, float& c1, float& c2, float& c3,
                                         uint32_t a0, uint32_t a1, uint32_t a2, uint32_t a3,
                                         uint32_t b0, uint32_t b1) {
    asm volatile("mma.sync.aligned.m16n8k16.row.col.f32.f16.f16.f32 "
                 "{%0,%1,%2,%3},{%4,%5,%6,%7},{%8,%9},{%0,%1,%2,%3};"
                 : "+f"(c0), "+f"(c1), "+f"(c2), "+f"(c3)
                 : "r"(a0), "r"(a1), "r"(a2), "r"(a3), "r"(b0), "r"(b1));
}

__global__ void __launch_bounds__(256) k_gemm(float* __restrict__ out) {
    __shared__ __align__(16) __half As[2][BM * KSTRIDE];
    __shared__ __align__(16) __half Bs[2][BN * KSTRIDE];

    const int tid    = threadIdx.x;
    const int lane   = tid & 31;
    const int wid    = tid >> 5;
    const int warp_m = wid >> 2;   // 0..1  -> 64-row slab
    const int warp_n = wid & 3;    // 0..3  -> 32-col slab
    const int bm     = blockIdx.y * BM;
    const int bn     = blockIdx.x * BN;

    float acc[4][4][4];
#pragma unroll
    for (int mi = 0; mi < 4; mi++)
#pragma unroll
        for (int ni = 0; ni < 4; ni++)
#pragma unroll
            for (int r = 0; r < 4; r++) acc[mi][ni][r] = 0.f;

    // per-thread cp.async chunk coords: 512 16B-chunks per tile / 256 threads = 2 each
    auto load_tiles = [&](int buf, int k0) {
#pragma unroll
        for (int i = 0; i < 2; i++) {
            int c   = i * 256 + tid;
            int row = c >> 2;
            int col = (c & 3) * 8;
            cp16(smem_u32(&As[buf][row * KSTRIDE + col]),
                 g_Xh + (size_t)(bm + row) * 4096 + k0 + col);
            cp16(smem_u32(&Bs[buf][row * KSTRIDE + col]),
                 g_Wq + (size_t)(bn + row) * 4096 + k0 + col);
        }
    };

    load_tiles(0, 0);
    asm volatile("cp.async.commit_group;");

    const int KT = 4096 / BK;  // 128
    for (int kt = 0; kt < KT; ++kt) {
        const int buf = kt & 1;
        if (kt + 1 < KT) {
            load_tiles(buf ^ 1, (kt + 1) * BK);
            asm volatile("cp.async.commit_group;");
            asm volatile("cp.async.wait_group 1;");
        } else {
            asm volatile("cp.async.wait_group 0;");
        }
        __syncthreads();

#pragma unroll
        for (int ks = 0; ks < 2; ++ks) {
            // A fragments: 4 m-tiles of 16x16
            uint32_t a[4][4];
#pragma unroll
            for (int mi = 0; mi < 4; mi++) {
                int r   = warp_m * 64 + mi * 16 + (lane & 15);
                int col = ks * 16 + (lane >> 4) * 8;
                ldm4(smem_u32(&As[buf][r * KSTRIDE + col]),
                     a[mi][0], a[mi][1], a[mi][2], a[mi][3]);
            }
            // B fragments: 4 n-tiles (k16 x n8), loaded 2 tiles per ldmatrix.x4
            uint32_t b[4][2];
#pragma unroll
            for (int np = 0; np < 2; np++) {
                int n   = warp_n * 32 + np * 16 + (lane >> 4) * 8 + (lane & 7);
                int col = ks * 16 + ((lane >> 3) & 1) * 8;
                uint32_t r0, r1, r2, r3;
                ldm4(smem_u32(&Bs[buf][n * KSTRIDE + col]), r0, r1, r2, r3);
                b[np * 2][0]     = r0;  b[np * 2][1]     = r1;
                b[np * 2 + 1][0] = r2;  b[np * 2 + 1][1] = r3;
            }
#pragma unroll
            for (int mi = 0; mi < 4; mi++)
#pragma unroll
                for (int ni = 0; ni < 4; ni++)
                    mma16816(acc[mi][ni][0], acc[mi][ni][1], acc[mi][ni][2], acc[mi][ni][3],
                             a[mi][0], a[mi][1], a[mi][2], a[mi][3],
                             b[ni][0], b[ni][1]);
        }
        __syncthreads();
    }

    const float scale = g_scale;
#pragma unroll
    for (int mi = 0; mi < 4; mi++) {
        int row0 = bm + warp_m * 64 + mi * 16 + (lane >> 2);
#pragma unroll
        for (int ni = 0; ni < 4; ni++) {
            int col = bn + warp_n * 32 + ni * 8 + (lane & 3) * 2;
            float2 v0 = make_float2(acc[mi][ni][0] * scale, acc[mi][ni][1] * scale);
            float2 v1 = make_float2(acc[mi][ni][2] * scale, acc[mi][ni][3] * scale);
            *(float2*)&out[(size_t)row0 * 4096 + col]       = v0;
            *(float2*)&out[(size_t)(row0 + 8) * 4096 + col] = v1;
        }
    }
}

// ---------------------------------------------------------------- launch
extern "C" void kernel_launch(void* const* d_in, const int* in_sizes, int n_in,
                              void* d_out, int out_size) {
    const float* x = (const float*)d_in[0];
    const float* W = (const float*)d_in[1];
    float* out = (float*)d_out;

    k_absum_rows<<<4096, 256>>>(W);
    k_finalize_scale<<<1, 256>>>();
    k_conv_x<<<32768, 256>>>((const float4*)x);
    k_quant_w<<<16384, 256>>>((const float4*)W);

    dim3 grid(4096 / BN, 8192 / BM);  // (32, 64)
    k_gemm<<<grid, 256>>>(out);
}

// round 3
// speedup vs baseline: 1.6452x; 1.6452x over previous
#include <cuda_runtime.h>
#include <cuda_fp16.h>
#include <cstdint>

// BitLinear: scale = mean|W|; Wq = round(W/(scale+eps)); y = (x @ Wq^T) * scale
// x: [8192, 4096] f32, W: [4096, 4096] f32, out: [8192, 4096] f32
//
// R3: mma.sync HMMA GEMM (tcgen05 not compilable: harness PTX targets sm_103,
// not sm_103a). Operands pre-quantized to fp16, pre-blocked + SW128-swizzled
// so a single producer thread feeds smem with cp.async.bulk (no LDGSTS).
// 128x128x64 tiles, 3-stage mbarrier pipeline, warp tile 64x32.

#define EPS_F 1e-5f

__device__ float  g_partial[4096];
__device__ float  g_scale;
__device__ float  g_inv;
// blocked+swizzled fp16 operands, 16KB blocks = [128 rows][64 halves] SW128:
//   g_Xa: [64 m_tiles][64 k_chunks]  (64 MB)
//   g_Wb: [32 n_tiles][64 k_chunks]  (32 MB)
__device__ __align__(1024) __half g_Xa[8192u * 4096u];
__device__ __align__(1024) __half g_Wb[4096u * 4096u];

__host__ __device__ __forceinline__ uint32_t sw128(uint32_t off) {
    return off ^ ((off >> 3) & 0x70);
}

// ---------------------------------------------------------------- reductions
__global__ void k_absum_rows(const float* __restrict__ W) {
    int row = blockIdx.x;
    const float* p = W + (size_t)row * 4096;
    float s = 0.f;
    for (int i = threadIdx.x; i < 4096; i += 256) s += fabsf(p[i]);
    for (int o = 16; o > 0; o >>= 1) s += __shfl_down_sync(0xffffffffu, s, o);
    __shared__ float sm[8];
    if ((threadIdx.x & 31) == 0) sm[threadIdx.x >> 5] = s;
    __syncthreads();
    if (threadIdx.x < 8) {
        float v = sm[threadIdx.x];
        for (int o = 4; o > 0; o >>= 1) v += __shfl_down_sync(0xffu, v, o);
        if (threadIdx.x == 0) g_partial[row] = v;
    }
}

__global__ void k_finalize_scale() {
    float s = 0.f;
    for (int i = threadIdx.x; i < 4096; i += 256) s += g_partial[i];
    for (int o = 16; o > 0; o >>= 1) s += __shfl_down_sync(0xffffffffu, s, o);
    __shared__ float sm[8];
    if ((threadIdx.x & 31) == 0) sm[threadIdx.x >> 5] = s;
    __syncthreads();
    if (threadIdx.x < 8) {
        float v = sm[threadIdx.x];
        for (int o = 4; o > 0; o >>= 1) v += __shfl_down_sync(0xffu, v, o);
        if (threadIdx.x == 0) {
            float mean = v / 16777216.f;
            g_scale = mean;
            g_inv   = 1.f / (mean + EPS_F);
        }
    }
}

// ---------------------------------------------------------------- prepasses
// x -> fp16, blocked [m_tile=128 rows][k_chunk=64 halves], SW128 swizzled
__global__ void k_conv_x(const float4* __restrict__ X4) {
    int c  = blockIdx.x * 256 + threadIdx.x;   // 4,194,304 chunks of 8 halves
    int m  = c >> 9;
    int k8 = c & 511;
    const float4* src = X4 + (size_t)m * 1024 + k8 * 2;
    float4 v0 = src[0], v1 = src[1];
    __half2 h0 = __floats2half2_rn(v0.x, v0.y);
    __half2 h1 = __floats2half2_rn(v0.z, v0.w);
    __half2 h2 = __floats2half2_rn(v1.x, v1.y);
    __half2 h3 = __floats2half2_rn(v1.z, v1.w);
    uint4 u;
    u.x = *reinterpret_cast<uint32_t*>(&h0);
    u.y = *reinterpret_cast<uint32_t*>(&h1);
    u.z = *reinterpret_cast<uint32_t*>(&h2);
    u.w = *reinterpret_cast<uint32_t*>(&h3);
    int k   = k8 * 8;
    int blk = ((m >> 7) << 6) + (k >> 6);
    uint32_t off = ((m & 127) << 7) + ((k & 63) << 1);
    *reinterpret_cast<uint4*>((char*)g_Xa + (size_t)blk * 16384 + sw128(off)) = u;
}

// W -> quantized fp16, blocked [n_tile=128 rows][k_chunk=64 halves], SW128
__global__ void k_quant_w(const float4* __restrict__ W4) {
    float inv = g_inv;
    int c  = blockIdx.x * 256 + threadIdx.x;   // 2,097,152 chunks of 8 halves
    int o  = c >> 9;
    int k8 = c & 511;
    const float4* src = W4 + (size_t)o * 1024 + k8 * 2;
    float4 v0 = src[0], v1 = src[1];
    __half2 h0 = __floats2half2_rn(rintf(v0.x * inv), rintf(v0.y * inv));
    __half2 h1 = __floats2half2_rn(rintf(v0.z * inv), rintf(v0.w * inv));
    __half2 h2 = __floats2half2_rn(rintf(v1.x * inv), rintf(v1.y * inv));
    __half2 h3 = __floats2half2_rn(rintf(v1.z * inv), rintf(v1.w * inv));
    uint4 u;
    u.x = *reinterpret_cast<uint32_t*>(&h0);
    u.y = *reinterpret_cast<uint32_t*>(&h1);
    u.z = *reinterpret_cast<uint32_t*>(&h2);
    u.w = *reinterpret_cast<uint32_t*>(&h3);
    int k   = k8 * 8;
    int blk = ((o >> 7) << 6) + (k >> 6);
    uint32_t off = ((o & 127) << 7) + ((k & 63) << 1);
    *reinterpret_cast<uint4*>((char*)g_Wb + (size_t)blk * 16384 + sw128(off)) = u;
}

// ---------------------------------------------------------------- GEMM
__device__ __forceinline__ uint32_t smem_u32(const void* p) {
    return (uint32_t)__cvta_generic_to_shared(p);
}
__device__ __forceinline__ void mbar_init(uint32_t a, uint32_t cnt) {
    asm volatile("mbarrier.init.shared.b64 [%0], %1;" :: "r"(a), "r"(cnt) : "memory");
}
__device__ __forceinline__ void mbar_expect(uint32_t a, uint32_t bytes) {
    asm volatile("mbarrier.arrive.expect_tx.shared.b64 _, [%0], %1;"
                 :: "r"(a), "r"(bytes) : "memory");
}
__device__ __forceinline__ void mbar_wait(uint32_t a, uint32_t ph) {
    asm volatile(
        "{\n\t.reg .pred P;\n"
        "WL%=:\n\t"
        "mbarrier.try_wait.parity.shared.b64 P, [%0], %1, 0x989680;\n\t"
        "@P bra WD%=;\n\t"
        "bra WL%=;\n"
        "WD%=:\n\t}"
        :: "r"(a), "r"(ph) : "memory");
}
__device__ __forceinline__ void bulk_g2s(uint32_t dst, const void* src,
                                         uint32_t bytes, uint32_t mbar) {
    asm volatile(
        "cp.async.bulk.shared::cluster.global.mbarrier::complete_tx::bytes "
        "[%0], [%1], %2, [%3];"
        :: "r"(dst), "l"(src), "r"(bytes), "r"(mbar) : "memory");
}
__device__ __forceinline__ void ldm4(uint32_t addr, uint32_t& r0, uint32_t& r1,
                                     uint32_t& r2, uint32_t& r3) {
    asm volatile("ldmatrix.sync.aligned.m8n8.x4.shared.b16 {%0,%1,%2,%3}, [%4];"
                 : "=r"(r0), "=r"(r1), "=r"(r2), "=r"(r3) : "r"(addr));
}
__device__ __forceinline__ void mma16816(float& c0, float& c1, float& c2, float& c3,
                                         uint32_t a0, uint32_t a1, uint32_t a2, uint32_t a3,
                                         uint32_t b0, uint32_t b1) {
    asm volatile("mma.sync.aligned.m16n8k16.row.col.f32.f16.f16.f32 "
                 "{%0,%1,%2,%3},{%4,%5,%6,%7},{%8,%9},{%0,%1,%2,%3};"
                 : "+f"(c0), "+f"(c1), "+f"(c2), "+f"(c3)
                 : "r"(a0), "r"(a1), "r"(a2), "r"(a3), "r"(b0), "r"(b1));
}

#define NSTAGE 3
#define STG 16384
#define CTRL 1024
#define SMEM_TOTAL (CTRL + NSTAGE * 2 * STG)   // 99328

__global__ void __launch_bounds__(256, 2) k_gemm(float* __restrict__ out) {
    extern __shared__ __align__(1024) char smem[];
    uint32_t sb = (uint32_t)__cvta_generic_to_shared(smem);
    const int tid    = threadIdx.x;
    const int lane   = tid & 31;
    const int wid    = tid >> 5;
    const int warp_m = wid >> 2;
    const int warp_n = wid & 3;
    const int bn     = blockIdx.x;   // 0..31 (128-col tile)
    const int bm     = blockIdx.y;   // 0..63 (128-row tile)

    const uint32_t sA = sb + CTRL;                 // [stage][16KB]
    const uint32_t sB = sb + CTRL + NSTAGE * STG;  // [stage][16KB]
    const char* gA = (const char*)g_Xa + (size_t)bm * 64 * STG;
    const char* gB = (const char*)g_Wb + (size_t)bn * 64 * STG;

    if (tid == 0)
        for (int s = 0; s < NSTAGE; s++) mbar_init(sb + s * 8, 1);
    __syncthreads();

    // prologue: fill stages 0..NSTAGE-2
    if (tid == 0) {
#pragma unroll
        for (int j = 0; j < NSTAGE - 1; j++) {
            uint32_t fb = sb + j * 8;
            mbar_expect(fb, 2 * STG);
            bulk_g2s(sA + j * STG, gA + (size_t)j * STG, STG, fb);
            bulk_g2s(sB + j * STG, gB + (size_t)j * STG, STG, fb);
        }
    }

    float acc[4][4][4];
#pragma unroll
    for (int mi = 0; mi < 4; mi++)
#pragma unroll
        for (int ni = 0; ni < 4; ni++)
#pragma unroll
            for (int r = 0; r < 4; r++) acc[mi][ni][r] = 0.f;

    for (int i = 0; i < 64; ++i) {
        const int s = i % NSTAGE;
        mbar_wait(sb + s * 8, (i / NSTAGE) & 1);
        __syncthreads();   // everyone done with stage written next
        if (tid == 0 && i + NSTAGE - 1 < 64) {
            int j = i + NSTAGE - 1;
            int t = j % NSTAGE;
            uint32_t fb = sb + t * 8;
            mbar_expect(fb, 2 * STG);
            bulk_g2s(sA + t * STG, gA + (size_t)j * STG, STG, fb);
            bulk_g2s(sB + t * STG, gB + (size_t)j * STG, STG, fb);
        }
        const uint32_t a_base = sA + s * STG;
        const uint32_t b_base = sB + s * STG;

#pragma unroll
        for (int ks = 0; ks < 4; ++ks) {
            uint32_t a[4][4];
#pragma unroll
            for (int mi = 0; mi < 4; mi++) {
                int r   = warp_m * 64 + mi * 16 + (lane & 15);
                int col = ks * 16 + (lane >> 4) * 8;
                ldm4(a_base + sw128((uint32_t)(r * 128 + col * 2)),
                     a[mi][0], a[mi][1], a[mi][2], a[mi][3]);
            }
            uint32_t b[4][2];
#pragma unroll
            for (int np = 0; np < 2; np++) {
                int n   = warp_n * 32 + np * 16 + (lane >> 4) * 8 + (lane & 7);
                int col = ks * 16 + ((lane >> 3) & 1) * 8;
                uint32_t r0, r1, r2, r3;
                ldm4(b_base + sw128((uint32_t)(n * 128 + col * 2)), r0, r1, r2, r3);
                b[np * 2][0]     = r0;  b[np * 2][1]     = r1;
                b[np * 2 + 1][0] = r2;  b[np * 2 + 1][1] = r3;
            }
#pragma unroll
            for (int mi = 0; mi < 4; mi++)
#pragma unroll
                for (int ni = 0; ni < 4; ni++)
                    mma16816(acc[mi][ni][0], acc[mi][ni][1], acc[mi][ni][2], acc[mi][ni][3],
                             a[mi][0], a[mi][1], a[mi][2], a[mi][3],
                             b[ni][0], b[ni][1]);
        }
    }

    const float scale = g_scale;
#pragma unroll
    for (int mi = 0; mi < 4; mi++) {
        int row0 = bm * 128 + warp_m * 64 + mi * 16 + (lane >> 2);
#pragma unroll
        for (int ni = 0; ni < 4; ni++) {
            int col = bn * 128 + warp_n * 32 + ni * 8 + (lane & 3) * 2;
            float2 v0 = make_float2(acc[mi][ni][0] * scale, acc[mi][ni][1] * scale);
            float2 v1 = make_float2(acc[mi][ni][2] * scale, acc[mi][ni][3] * scale);
            *(float2*)&out[(size_t)row0 * 4096 + col]       = v0;
            *(float2*)&out[(size_t)(row0 + 8) * 4096 + col] = v1;
        }
    }
}

// ---------------------------------------------------------------- launch
extern "C" void kernel_launch(void* const* d_in, const int* in_sizes, int n_in,
                              void* d_out, int out_size) {
    const float* x = (const float*)d_in[0];
    const float* W = (const float*)d_in[1];
    float* out = (float*)d_out;

    k_absum_rows<<<4096, 256>>>(W);
    k_finalize_scale<<<1, 256>>>();
    k_conv_x<<<16384, 256>>>((const float4*)x);
    k_quant_w<<<8192, 256>>>((const float4*)W);

    cudaFuncSetAttribute(k_gemm, cudaFuncAttributeMaxDynamicSharedMemorySize, SMEM_TOTAL);
    dim3 grid(32, 64);   // (N/128, M/128)
    k_gemm<<<grid, 256, SMEM_TOTAL>>>(out);
}